// round 5
// baseline (speedup 1.0000x reference)
#include <cuda_runtime.h>
#include <cuda_fp16.h>
#include <cstdint>

#define CIN   672
#define COUT  128
#define HW    49
#define NB    4
#define NREAL 196         // NB*HW
#define NSP   56          // per-batch padded spatial
#define NPAD  224
#define KC    32
#define NKC   21
#define THREADS 512
#define GRID  256

#define LDAW  352         // A row stride in words (= 88 quads)
#define LDBW  20          // B row stride in words (5 quads -> conflict-free LDSM)

#define OFF_SS 0                       // float2[672] = 1344 words
#define OFF_A  1344
#define A_WORDS (COUT*LDAW)            // 45056
#define OFF_B0 (OFF_A + A_WORDS)       // 46400
#define B_WORDS (NPAD*LDBW)            // 4480
#define OFF_B1 (OFF_B0 + B_WORDS)      // 50880
#define SMEM_WORDS (OFF_B1 + B_WORDS)  // 55360
#define SMEM_BYTES (SMEM_WORDS*4)      // 221440
#define PS 225                         // epilogue payload stride (overlays smem)

__device__ __forceinline__ void hmma16816(float c[4],
    uint32_t a0, uint32_t a1, uint32_t a2, uint32_t a3, uint32_t b0, uint32_t b1)
{
    asm volatile(
        "mma.sync.aligned.m16n8k16.row.col.f32.f16.f16.f32 "
        "{%0,%1,%2,%3}, {%4,%5,%6,%7}, {%8,%9}, {%0,%1,%2,%3};"
        : "+f"(c[0]), "+f"(c[1]), "+f"(c[2]), "+f"(c[3])
        : "r"(a0), "r"(a1), "r"(a2), "r"(a3), "r"(b0), "r"(b1));
}
__device__ __forceinline__ void ldsm_x4(uint32_t& r0, uint32_t& r1,
                                        uint32_t& r2, uint32_t& r3, uint32_t addr)
{
    asm volatile("ldmatrix.sync.aligned.m8n8.x4.shared.b16 {%0,%1,%2,%3}, [%4];"
                 : "=r"(r0), "=r"(r1), "=r"(r2), "=r"(r3) : "r"(addr));
}
__device__ __forceinline__ void ldsm_x2(uint32_t& r0, uint32_t& r1, uint32_t addr)
{
    asm volatile("ldmatrix.sync.aligned.m8n8.x2.shared.b16 {%0,%1}, [%2];"
                 : "=r"(r0), "=r"(r1) : "r"(addr));
}
__device__ __forceinline__ uint32_t pack_h2(float lo, float hi) {
    __half2 h = __floats2half2_rn(lo, hi);
    return *reinterpret_cast<uint32_t*>(&h);
}
__device__ __forceinline__ uint32_t smem_u32(const void* p) {
    uint32_t a;
    asm("{ .reg .u64 t; cvta.to.shared.u64 t, %1; cvt.u32.u64 %0, t; }" : "=r"(a) : "l"(p));
    return a;
}

extern __shared__ uint32_t sm[];

__global__ void __launch_bounds__(THREADS, 1)
bn_conv_ldsm(const float* __restrict__ x,
             const float* __restrict__ gamma,
             const float* __restrict__ beta,
             const float* __restrict__ rmean,
             const float* __restrict__ rvar,
             const float* __restrict__ W,
             float* __restrict__ out)
{
    const int tid  = threadIdx.x;
    const int wid  = tid >> 5;
    const int lane = tid & 31;
    const int g = lane >> 2, t = lane & 3;
    const int m_base = (wid & 3) * 32;     // 4 warps over M=128
    const int n0     = (wid >> 2) * 56;    // 4 warps over N=224
    const uint32_t sb = smem_u32(sm);

    float2* ssc = (float2*)(sm + OFF_SS);
    const float* sscf = (const float*)ssc;

    // ---- prologue: BN fold ----
    for (int c = tid; c < CIN; c += THREADS) {
        float inv = rsqrtf(rvar[c] + 1e-5f);
        float s = gamma[c] * inv;
        ssc[c] = make_float2(s, beta[c] - rmean[c] * s);
    }
    // zero both B buffers (covers padded rows permanently)
    for (int i = tid; i < 2 * B_WORDS; i += THREADS) sm[OFF_B0 + i] = 0u;

    // ---- stage full W as fp16, quad-swizzled: 10752 quads = 512*21 ----
    #pragma unroll
    for (int it = 0; it < 21; it++) {
        int u = tid + it * THREADS;
        int m = u / 84, qk = u - m * 84;
        const float* ws = W + (size_t)m * CIN + qk * 8;
        float4 w0 = *(const float4*)ws;
        float4 w1 = *(const float4*)(ws + 4);
        uint4 q;
        q.x = pack_h2(w0.x, w0.y); q.y = pack_h2(w0.z, w0.w);
        q.z = pack_h2(w1.x, w1.y); q.w = pack_h2(w1.z, w1.w);
        int qpos = (qk & ~7) | ((qk & 7) ^ (m & 7));
        *(uint4*)(sm + OFF_A + m * LDAW + qpos * 4) = q;
    }

    // ---- per-thread B staging constants (1568 slots = 8 k-quads x 196 n) ----
    int xoff[4], bw[4], cq[4];
    #pragma unroll
    for (int j = 0; j < 4; j++) {
        int i = tid + j * THREADS;
        if (i > 1567) i = 1567;
        int p = i / NREAL;
        int n = i - p * NREAL;
        int bloc = n / HW, s = n - bloc * HW;
        xoff[j] = (bloc * CIN + p * 4) * HW + s;
        bw[j]   = (bloc * NSP + s) * LDBW + p * 2;
        cq[j]   = p * 4;
    }
    const bool v3 = (tid < 32);

    // ---- lane-constant LDSM address pieces ----
    // A: rows m_base(+mt*16) + (lane&7) + ((lane>>3)&1)*8 ; quad +((lane>>4)&1)
    const int arow  = (lane & 7) + ((lane >> 3) & 1) * 8;
    const int aqsel = (lane >> 4) & 1;
    const int alow  = lane & 7;
    // B: rows n0 + nt*8 + (lane&7) + ((lane>>4)&1)*8 ; quad ks*2 + ((lane>>3)&1)
    const int brow  = (lane & 7) + ((lane >> 4) & 1) * 8;
    const int bqsel = (lane >> 3) & 1;

    const float* xb = x + (size_t)blockIdx.x * NB * CIN * HW;
    __syncthreads();

    float acc[2][7][4];
    #pragma unroll
    for (int mt = 0; mt < 2; mt++)
        #pragma unroll
        for (int nt = 0; nt < 7; nt++)
            #pragma unroll
            for (int i = 0; i < 4; i++) acc[mt][nt][i] = 0.0f;

    float xv[4][4];

    #pragma unroll 1
    for (int kc = -1; kc < NKC; kc++) {
        const int kcn = kc + 1;

        // ---- issue x LDGs for chunk kcn ----
        if (kcn < NKC) {
            const int xadd = kcn * (KC * HW);
            #pragma unroll
            for (int j = 0; j < 4; j++) {
                if (j < 3 || v3) {
                    const float* px = xb + xoff[j] + xadd;
                    xv[j][0] = px[0];
                    xv[j][1] = px[HW];
                    xv[j][2] = px[2 * HW];
                    xv[j][3] = px[3 * HW];
                }
            }
        }

        // ---- MMA on chunk kc ----
        if (kc >= 0) {
            const uint32_t boffw = (kc & 1) ? OFF_B1 : OFF_B0;
            #pragma unroll
            for (int ks = 0; ks < 2; ks++) {
                // A fragments: 2 LDSM.x4
                const int qk = kc * 4 + ks * 2 + aqsel;
                const int qpos = (qk & ~7) | ((qk & 7) ^ alow);
                uint32_t a[2][4];
                #pragma unroll
                for (int mt = 0; mt < 2; mt++) {
                    uint32_t addr = sb + 4 * (OFF_A + (m_base + mt * 16 + arow) * LDAW + qpos * 4);
                    ldsm_x4(a[mt][0], a[mt][1], a[mt][2], a[mt][3], addr);
                }
                // B fragments: 3 LDSM.x4 + 1 LDSM.x2
                uint32_t b[7][2];
                const uint32_t bbase = sb + 4 * (boffw + (n0 + brow) * LDBW + (ks * 2 + bqsel) * 4);
                #pragma unroll
                for (int np = 0; np < 3; np++) {
                    ldsm_x4(b[2 * np][0], b[2 * np][1], b[2 * np + 1][0], b[2 * np + 1][1],
                            bbase + 4 * (np * 16 * LDBW));
                }
                {
                    // x2 uses lanes 0-15; keep lanes 16-31 addrs in-bounds
                    uint32_t addr6 = bbase + 4 * (6 * 8 * LDBW);
                    if (brow >= 8) addr6 -= 4 * (8 * LDBW);
                    ldsm_x2(b[6][0], b[6][1], addr6);
                }
                #pragma unroll
                for (int nt = 0; nt < 7; nt++) {
                    hmma16816(acc[0][nt], a[0][0], a[0][1], a[0][2], a[0][3], b[nt][0], b[nt][1]);
                    hmma16816(acc[1][nt], a[1][0], a[1][1], a[1][2], a[1][3], b[nt][0], b[nt][1]);
                }
            }
        }

        // ---- BN + ReLU + cvt + STS chunk kcn ----
        if (kcn < NKC) {
            uint32_t* Bn = sm + ((kcn & 1) ? OFF_B1 : OFF_B0);
            #pragma unroll
            for (int j = 0; j < 4; j++) {
                if (j < 3 || v3) {
                    const int c = kcn * KC + cq[j];
                    float4 s0 = *(const float4*)(sscf + 2 * c);
                    float4 s1 = *(const float4*)(sscf + 2 * c + 4);
                    float h0 = fmaxf(fmaf(xv[j][0], s0.x, s0.y), 0.0f);
                    float h1 = fmaxf(fmaf(xv[j][1], s0.z, s0.w), 0.0f);
                    float h2 = fmaxf(fmaf(xv[j][2], s1.x, s1.y), 0.0f);
                    float h3 = fmaxf(fmaf(xv[j][3], s1.z, s1.w), 0.0f);
                    uint2 hb;
                    hb.x = pack_h2(h0, h1);
                    hb.y = pack_h2(h2, h3);
                    *(uint2*)(Bn + bw[j]) = hb;
                }
            }
        }
        __syncthreads();
    }

    // ---- epilogue: acc -> SMEM payload P[o][n] -> coalesced STG ----
    float* P = (float*)sm;
    #pragma unroll
    for (int mt = 0; mt < 2; mt++) {
        const int rb = m_base + mt * 16 + g;
        #pragma unroll
        for (int nt = 0; nt < 7; nt++) {
            const int cb = n0 + nt * 8 + 2 * t;
            P[rb * PS + cb]           = acc[mt][nt][0];
            P[rb * PS + cb + 1]       = acc[mt][nt][1];
            P[(rb + 8) * PS + cb]     = acc[mt][nt][2];
            P[(rb + 8) * PS + cb + 1] = acc[mt][nt][3];
        }
    }
    __syncthreads();

    float* ob = out + (size_t)blockIdx.x * NB * COUT * HW;
    #pragma unroll 7
    for (int it = 0; it < 49; it++) {
        int f = tid + it * THREADS;              // 25088 = 512*49 exactly
        int bloc = f / (COUT * HW);
        int r = f - bloc * (COUT * HW);
        int o = r / HW;
        int s = r - o * HW;
        ob[f] = P[o * PS + bloc * NSP + s];
    }
}

extern "C" void kernel_launch(void* const* d_in, const int* in_sizes, int n_in,
                              void* d_out, int out_size)
{
    const float* x     = (const float*)d_in[0];
    const float* gamma = (const float*)d_in[1];
    const float* beta  = (const float*)d_in[2];
    const float* rmean = (const float*)d_in[3];
    const float* rvar  = (const float*)d_in[4];
    const float* W     = (const float*)d_in[5];
    float* out = (float*)d_out;

    cudaFuncSetAttribute(bn_conv_ldsm,
                         cudaFuncAttributeMaxDynamicSharedMemorySize, SMEM_BYTES);
    bn_conv_ldsm<<<GRID, THREADS, SMEM_BYTES>>>(x, gamma, beta, rmean, rvar, W, out);
}